// round 2
// baseline (speedup 1.0000x reference)
#include <cuda_runtime.h>
#include <cuda_bf16.h>
#include <math.h>

#define NN 100000
#define NE 1600000
#define NFEAT 256
#define NHID1 128
#define NCLASS 64
#define NGRAPH 64

// ---------------- scratch (device globals; no allocation) ----------------
__device__ int   d_idx64;             // 1 if int inputs are int64, else int32
__device__ float d_deg[NN];
__device__ float d_dinv[NN];
__device__ int   d_counts[NN];
__device__ int   d_rowstart[NN];
__device__ int   d_cursor[NN];
__device__ int   d_blockSums[128];
__device__ int   d_csr_src[NE];
__device__ float d_csr_val[NE];
__device__ float d_xw1[NN * NHID1];   // 51.2 MB
__device__ float d_h1[NN * NHID1];    // 51.2 MB
__device__ float d_xw2[NN * NCLASS];  // 25.6 MB
__device__ float d_h2[NN * NCLASS];   // 25.6 MB
__device__ int   d_starts[NGRAPH + 1];
__device__ float d_pooled[NGRAPH * NCLASS];

// index load that works for int32 or int64 (little-endian low word; values < 2^31)
__device__ __forceinline__ int load_idx(const int* __restrict__ p, long long i) {
    return d_idx64 ? p[2 * i] : p[i];
}

// ---------------- dtype detection ----------------
// If data is int64 (values < 2^31), every odd 32-bit word is 0.
// If int32, odd words are random node ids — P(128 zeros) ~ 0.
__global__ void detect_kernel(const int* __restrict__ ei) {
    if (threadIdx.x == 0 && blockIdx.x == 0) {
        int allzero = 1;
        for (int i = 0; i < 128; i++)
            if (ei[2 * i + 1] != 0) { allzero = 0; break; }
        d_idx64 = allzero;
    }
}

// ---------------- degree / dinv ----------------
__global__ void init_kernel() {
    int i = blockIdx.x * blockDim.x + threadIdx.x;
    if (i < NN) { d_deg[i] = 1.0f; d_counts[i] = 0; }  // self-loop weight 1
}

__global__ void edge_deg_kernel(const int* __restrict__ ei,
                                const float* __restrict__ ew) {
    int e = blockIdx.x * blockDim.x + threadIdx.x;
    if (e < NE) {
        int c = load_idx(ei, (long long)NE + e);   // col = target
        atomicAdd(&d_deg[c], ew[e]);
        atomicAdd(&d_counts[c], 1);
    }
}

__global__ void dinv_kernel() {
    int i = blockIdx.x * blockDim.x + threadIdx.x;
    if (i < NN) d_dinv[i] = rsqrtf(d_deg[i]);   // deg >= 1 always (self loop)
}

// ---------------- prefix sum (3 kernels) ----------------
__global__ void scan_block_kernel() {
    __shared__ int s[1024];
    int i = blockIdx.x * 1024 + threadIdx.x;
    int v = (i < NN) ? d_counts[i] : 0;
    s[threadIdx.x] = v;
    __syncthreads();
    for (int off = 1; off < 1024; off <<= 1) {
        int t = (threadIdx.x >= off) ? s[threadIdx.x - off] : 0;
        __syncthreads();
        s[threadIdx.x] += t;
        __syncthreads();
    }
    if (i < NN) d_rowstart[i] = s[threadIdx.x] - v;   // exclusive
    if (threadIdx.x == 1023) d_blockSums[blockIdx.x] = s[1023];
}

__global__ void scan_sums_kernel(int nb) {
    if (threadIdx.x == 0 && blockIdx.x == 0) {
        int acc = 0;
        for (int b = 0; b < nb; b++) { int t = d_blockSums[b]; d_blockSums[b] = acc; acc += t; }
    }
}

__global__ void add_offsets_kernel() {
    int i = blockIdx.x * 1024 + threadIdx.x;
    if (i < NN) {
        int v = d_rowstart[i] + d_blockSums[blockIdx.x];
        d_rowstart[i] = v;
        d_cursor[i]  = v;
    }
}

// ---------------- CSR fill ----------------
__global__ void csr_fill_kernel(const int* __restrict__ ei,
                                const float* __restrict__ ew) {
    int e = blockIdx.x * blockDim.x + threadIdx.x;
    if (e < NE) {
        int r = load_idx(ei, e);
        int c = load_idx(ei, (long long)NE + e);
        int pos = atomicAdd(&d_cursor[c], 1);
        d_csr_src[pos] = r;
        d_csr_val[pos] = d_dinv[r] * ew[e];
    }
}

// ---------------- SGEMM: C[M,N] = A[M,K] @ B[K,N] ----------------
// BM=64, BK=16, 16x16 threads, TM=4, TN = 4 or 8 (as TN/4 chunks of 4 cols, 64 apart)
template <int BN, int TN>
__global__ void sgemm_kernel(const float* __restrict__ A, const float* __restrict__ B,
                             float* __restrict__ C, int M, int K, int N) {
    const int BM = 64, BK = 16;
    __shared__ __align__(16) float As[BK][BM];
    __shared__ __align__(16) float Bs[BK][BN];
    const int tx = threadIdx.x, ty = threadIdx.y;
    const int tid = ty * 16 + tx;
    const int rowBase = blockIdx.y * BM;
    const int colBase = blockIdx.x * BN;
    const int NCH = TN / 4;

    float acc[4][TN];
#pragma unroll
    for (int i = 0; i < 4; i++)
#pragma unroll
        for (int j = 0; j < TN; j++) acc[i][j] = 0.f;

    const int am = tid >> 2;        // 0..63
    const int ak = (tid & 3) * 4;   // 0,4,8,12

    for (int k0 = 0; k0 < K; k0 += BK) {
        float4 av = make_float4(0.f, 0.f, 0.f, 0.f);
        if (rowBase + am < M)
            av = *reinterpret_cast<const float4*>(&A[(size_t)(rowBase + am) * K + k0 + ak]);
        As[ak + 0][am] = av.x; As[ak + 1][am] = av.y;
        As[ak + 2][am] = av.z; As[ak + 3][am] = av.w;
#pragma unroll
        for (int l = 0; l < BN / 64; l++) {
            int idx = tid + l * 256;
            int bk = idx / (BN / 4);
            int bn = (idx % (BN / 4)) * 4;
            float4 bv = *reinterpret_cast<const float4*>(&B[(size_t)(k0 + bk) * N + colBase + bn]);
            *reinterpret_cast<float4*>(&Bs[bk][bn]) = bv;
        }
        __syncthreads();
#pragma unroll
        for (int k = 0; k < BK; k++) {
            float4 a4 = *reinterpret_cast<float4*>(&As[k][ty * 4]);
            float ra[4] = {a4.x, a4.y, a4.z, a4.w};
#pragma unroll
            for (int c = 0; c < NCH; c++) {
                float4 b4 = *reinterpret_cast<float4*>(&Bs[k][c * 64 + tx * 4]);
                float rb[4] = {b4.x, b4.y, b4.z, b4.w};
#pragma unroll
                for (int i = 0; i < 4; i++)
#pragma unroll
                    for (int j = 0; j < 4; j++)
                        acc[i][c * 4 + j] = fmaf(ra[i], rb[j], acc[i][c * 4 + j]);
            }
        }
        __syncthreads();
    }
#pragma unroll
    for (int i = 0; i < 4; i++) {
        int row = rowBase + ty * 4 + i;
        if (row < M) {
#pragma unroll
            for (int c = 0; c < NCH; c++) {
                float4 o = make_float4(acc[i][c * 4 + 0], acc[i][c * 4 + 1],
                                       acc[i][c * 4 + 2], acc[i][c * 4 + 3]);
                *reinterpret_cast<float4*>(&C[(size_t)row * N + colBase + c * 64 + tx * 4]) = o;
            }
        }
    }
}

// ---------------- CSR gather + bias + relu (block per node, thread per feature) ----
template <int F>
__global__ void gather_relu_kernel(const float* __restrict__ xw,
                                   const float* __restrict__ bias,
                                   float* __restrict__ out) {
    int node = blockIdx.x;
    int f = threadIdx.x;
    float dn = d_dinv[node];
    int rs = d_rowstart[node];
    int cnt = d_counts[node];
    float acc = xw[(size_t)node * F + f] * dn * dn;   // self loop
    for (int e = rs; e < rs + cnt; e++) {
        int src = d_csr_src[e];
        float c = d_csr_val[e] * dn;
        acc = fmaf(__ldg(&xw[(size_t)src * F + f]), c, acc);
    }
    out[(size_t)node * F + f] = fmaxf(acc + bias[f], 0.f);
}

// ---------------- graph boundaries (batch is sorted) ----------------
__global__ void graph_starts_kernel(const int* __restrict__ batch) {
    int g = threadIdx.x;
    if (g > NGRAPH) return;
    if (g == NGRAPH) { d_starts[g] = NN; return; }
    int lo = 0, hi = NN;
    while (lo < hi) {
        int mid = (lo + hi) >> 1;
        if (load_idx(batch, mid) < g) lo = mid + 1; else hi = mid;
    }
    d_starts[g] = lo;
}

// ---------------- pooling: block per graph ----------------
__global__ void pool_kernel() {
    int g = blockIdx.x;
    int f = threadIdx.x;   // 0..63
    int s0 = d_starts[g], s1 = d_starts[g + 1];
    float a0 = 0.f, a1 = 0.f, a2 = 0.f, a3 = 0.f;
    int n = s0;
    for (; n + 3 < s1; n += 4) {
        a0 += d_h2[(size_t)(n + 0) * NCLASS + f];
        a1 += d_h2[(size_t)(n + 1) * NCLASS + f];
        a2 += d_h2[(size_t)(n + 2) * NCLASS + f];
        a3 += d_h2[(size_t)(n + 3) * NCLASS + f];
    }
    for (; n < s1; ++n) a0 += d_h2[(size_t)n * NCLASS + f];
    d_pooled[g * NCLASS + f] = (a0 + a1) + (a2 + a3);
}

// ---------------- tiny MLP head + log_softmax + argmax ----------------
__global__ void head_kernel(const float* __restrict__ l1w, const float* __restrict__ l1b,
                            const float* __restrict__ l2w, const float* __restrict__ l2b,
                            float* __restrict__ out) {
    int g = threadIdx.x;
    if (g >= NGRAPH) return;
    float h[64];
#pragma unroll 4
    for (int j = 0; j < 64; j++) {
        float acc = l1b[j];
        for (int k = 0; k < 64; k++)
            acc = fmaf(d_pooled[g * 64 + k], l1w[k * 64 + j], acc);
        h[j] = fmaxf(acc, 0.f);
    }
    float o0 = l2b[0], o1 = l2b[1];
    for (int k = 0; k < 64; k++) {
        o0 = fmaf(h[k], l2w[k * 2 + 0], o0);
        o1 = fmaf(h[k], l2w[k * 2 + 1], o1);
    }
    float m = fmaxf(o0, o1);
    float lse = m + logf(expf(o0 - m) + expf(o1 - m));
    // layout: Y_prob [64*2] | Y_hat [64] | out [64*2]
    out[g * 2 + 0] = o0 - lse;
    out[g * 2 + 1] = o1 - lse;
    out[128 + g] = (o1 > o0) ? 1.0f : 0.0f;
    out[192 + g * 2 + 0] = o0;
    out[192 + g * 2 + 1] = o1;
}

// ---------------- launch ----------------
extern "C" void kernel_launch(void* const* d_in, const int* in_sizes, int n_in,
                              void* d_out, int out_size) {
    const float* x     = (const float*)d_in[0];
    const int*   ei    = (const int*)d_in[1];
    const float* ew    = (const float*)d_in[2];
    const int*   batch = (const int*)d_in[3];
    const float* W1 = (const float*)d_in[4];
    const float* b1 = (const float*)d_in[5];
    const float* W2 = (const float*)d_in[6];
    const float* b2 = (const float*)d_in[7];
    const float* l1w = (const float*)d_in[8];
    const float* l1b = (const float*)d_in[9];
    const float* l2w = (const float*)d_in[10];
    const float* l2b = (const float*)d_in[11];
    float* out = (float*)d_out;

    detect_kernel<<<1, 32>>>(ei);
    init_kernel<<<(NN + 255) / 256, 256>>>();
    edge_deg_kernel<<<(NE + 255) / 256, 256>>>(ei, ew);
    dinv_kernel<<<(NN + 255) / 256, 256>>>();

    const int NB = (NN + 1023) / 1024;   // 98
    scan_block_kernel<<<NB, 1024>>>();
    scan_sums_kernel<<<1, 32>>>(NB);
    add_offsets_kernel<<<NB, 1024>>>();

    csr_fill_kernel<<<(NE + 255) / 256, 256>>>(ei, ew);

    // layer 1: xw1 = x @ W1 ; h1 = relu(agg(xw1) + b1)
    {
        float* xw1; cudaGetSymbolAddress((void**)&xw1, d_xw1);
        float* h1;  cudaGetSymbolAddress((void**)&h1, d_h1);
        dim3 grid(NHID1 / 128, (NN + 63) / 64);
        sgemm_kernel<128, 8><<<grid, dim3(16, 16)>>>(x, W1, xw1, NN, NFEAT, NHID1);
        gather_relu_kernel<NHID1><<<NN, NHID1>>>(xw1, b1, h1);
    }
    // layer 2: xw2 = h1 @ W2 ; h2 = relu(agg(xw2) + b2)
    {
        float* h1;  cudaGetSymbolAddress((void**)&h1, d_h1);
        float* xw2; cudaGetSymbolAddress((void**)&xw2, d_xw2);
        float* h2;  cudaGetSymbolAddress((void**)&h2, d_h2);
        dim3 grid(NCLASS / 64, (NN + 63) / 64);
        sgemm_kernel<64, 4><<<grid, dim3(16, 16)>>>(h1, W2, xw2, NN, NHID1, NCLASS);
        gather_relu_kernel<NCLASS><<<NN, NCLASS>>>(xw2, b2, h2);
    }

    graph_starts_kernel<<<1, NGRAPH + 1>>>(batch);
    pool_kernel<<<NGRAPH, NCLASS>>>();
    head_kernel<<<1, 64>>>(l1w, l1b, l2w, l2b, out);
}